// round 3
// baseline (speedup 1.0000x reference)
#include <cuda_runtime.h>
#include <cuda_bf16.h>
#include <cstdint>

#define Bn 8
#define CN 64
#define CL 32
#define CH 128
#define Himg 256
#define HMimg 512
#define SLOPE 0.2f
#define GAINF 1.4142135623730951f
#define EPSV 1e-5f

// tile: 8 rows x 16 cols = 128 pixels per block
#define TH 8
#define TW 16
#define NPX 128

// smem layout (bytes)
#define OFF_B1 0            // 2048 u32 = 8192
#define OFF_B2 8192         // 8192 u32 = 32768
#define OFF_V 40960         // 128*40 bf16 = 10240
#define OFF_MISC 51200      // 396 floats (mu64,rstd64,biasH128,biasGB128,a12)
#define OFF_REGION 52784    // union: h[128][136] bf16 (34816) | raw(36608)+interm(13312)=49920
#define OFF_RAW OFF_REGION
#define OFF_INT (OFF_REGION + 36608)
#define SMEM_TOTAL (OFF_REGION + 49920)   // 102704

__device__ float g_mu[512];
__device__ float g_rstd[512];
__device__ float g_a[12];
__device__ uint4 g_fB1[512];    // 2048 u32: [kt2][nt16][lane32][pair2] bf16x2
__device__ uint4 g_fB2[2048];   // 8192 u32: [kt8][nt16][lane32][pair2] bf16x2

static __device__ __forceinline__ unsigned pack_bf16x2(float a, float b) {
    __nv_bfloat162 t = __floats2bfloat162_rn(a, b);
    return *reinterpret_cast<unsigned*>(&t);
}

// ---------------- prep: filter factorization + weight fragments ----------------
__global__ void prep_kernel(const float* __restrict__ F,
                            const float* __restrict__ w_shared,
                            const float* __restrict__ w_gamma,
                            const float* __restrict__ w_beta) {
    int tid = threadIdx.x;
    // F = outer(g,g); flipped 1D filter a[i] = g[11-i] = F[11-i][5]/sqrt(F[5][5])
    if (tid < 12) {
        g_a[tid] = F[(11 - tid) * 12 + 5] * rsqrtf(F[5 * 12 + 5]);
    }
    unsigned* B1 = reinterpret_cast<unsigned*>(g_fB1);
    for (int idx = tid; idx < 2048; idx += blockDim.x) {
        int pair = idx & 1;
        int lane = (idx >> 1) & 31;
        int nt = (idx >> 6) & 15;
        int kt = idx >> 10;
        int gid = lane >> 2, tig = lane & 3;
        int n = nt * 8 + gid;
        int k = kt * 16 + tig * 2 + pair * 8;
        B1[idx] = pack_bf16x2(w_shared[n * CL + k], w_shared[n * CL + k + 1]);
    }
    unsigned* B2 = reinterpret_cast<unsigned*>(g_fB2);
    for (int idx = tid; idx < 8192; idx += blockDim.x) {
        int pair = idx & 1;
        int lane = (idx >> 1) & 31;
        int nt = (idx >> 6) & 15;
        int kt = idx >> 10;
        int gid = lane >> 2, tig = lane & 3;
        int n = nt * 8 + gid;
        int k = kt * 16 + tig * 2 + pair * 8;
        float v0, v1;
        if (n < 64) { v0 = w_gamma[n * CH + k]; v1 = w_gamma[n * CH + k + 1]; }
        else        { v0 = w_beta[(n - 64) * CH + k]; v1 = w_beta[(n - 64) * CH + k + 1]; }
        B2[idx] = pack_bf16x2(v0, v1);
    }
}

// ---------------- instance-norm stats ----------------
__global__ void stats_kernel(const float* __restrict__ x) {
    int bc = blockIdx.x;
    const float4* xp = reinterpret_cast<const float4*>(x + (size_t)bc * 65536);
    float s = 0.f, q = 0.f;
    for (int i = threadIdx.x; i < 16384; i += 256) {
        float4 v = xp[i];
        s += (v.x + v.y) + (v.z + v.w);
        q += v.x * v.x + v.y * v.y + v.z * v.z + v.w * v.w;
    }
#pragma unroll
    for (int o = 16; o > 0; o >>= 1) {
        s += __shfl_down_sync(0xffffffffu, s, o);
        q += __shfl_down_sync(0xffffffffu, q, o);
    }
    __shared__ float ws[8], wq[8];
    int w = threadIdx.x >> 5;
    if ((threadIdx.x & 31) == 0) { ws[w] = s; wq[w] = q; }
    __syncthreads();
    if (threadIdx.x == 0) {
        float S = 0.f, Q = 0.f;
#pragma unroll
        for (int i = 0; i < 8; i++) { S += ws[i]; Q += wq[i]; }
        float mu = S * (1.f / 65536.f);
        float var = Q * (1.f / 65536.f) - mu * mu;
        g_mu[bc] = mu;
        g_rstd[bc] = rsqrtf(var + EPSV);
    }
}

// ---------------- mma helpers ----------------
static __device__ __forceinline__ void ldsm4(unsigned r[4], unsigned addr) {
    asm volatile("ldmatrix.sync.aligned.m8n8.x4.shared.b16 {%0,%1,%2,%3}, [%4];"
                 : "=r"(r[0]), "=r"(r[1]), "=r"(r[2]), "=r"(r[3])
                 : "r"(addr) : "memory");
}
static __device__ __forceinline__ void mma_bf16(float c[4], const unsigned a[4],
                                                unsigned b0, unsigned b1) {
    asm("mma.sync.aligned.m16n8k16.row.col.f32.bf16.bf16.f32 "
        "{%0,%1,%2,%3}, {%4,%5,%6,%7}, {%8,%9}, {%0,%1,%2,%3};"
        : "+f"(c[0]), "+f"(c[1]), "+f"(c[2]), "+f"(c[3])
        : "r"(a[0]), "r"(a[1]), "r"(a[2]), "r"(a[3]), "r"(b0), "r"(b1));
}

// ---------------- fused main kernel ----------------
__global__ void __launch_bounds__(256, 2)
main_kernel(const float* __restrict__ x,
            const float* __restrict__ hm,
            const float* __restrict__ b_shared,
            const float* __restrict__ b_gamma,
            const float* __restrict__ b_beta,
            float* __restrict__ out) {
    extern __shared__ char smem[];
    unsigned* sB1 = reinterpret_cast<unsigned*>(smem + OFF_B1);
    unsigned* sB2 = reinterpret_cast<unsigned*>(smem + OFF_B2);
    __nv_bfloat16* sv = reinterpret_cast<__nv_bfloat16*>(smem + OFF_V);     // [128][40]
    float* sMisc = reinterpret_cast<float*>(smem + OFF_MISC);
    float* muS = sMisc;          // 64
    float* rstdS = sMisc + 64;   // 64
    float* biasH = sMisc + 128;  // 128
    float* biasGB = sMisc + 256; // 128
    float* aS = sMisc + 384;     // 12
    __nv_bfloat16* sh = reinterpret_cast<__nv_bfloat16*>(smem + OFF_REGION); // [128][136]
    float* sraw = reinterpret_cast<float*>(smem + OFF_RAW);                  // [8][26][44]
    float* sint = reinterpret_cast<float*>(smem + OFF_INT);                  // [8][26][16]

    const int tid = threadIdx.x;
    const int b = blockIdx.z;
    const int x0 = blockIdx.x * TW;
    const int y0 = blockIdx.y * TH;

    // ---- stage constants / weights ----
    {
        uint4* d1 = reinterpret_cast<uint4*>(smem + OFF_B1);
        for (int i = tid; i < 512; i += 256) d1[i] = g_fB1[i];
        uint4* d2 = reinterpret_cast<uint4*>(smem + OFF_B2);
        for (int i = tid; i < 2048; i += 256) d2[i] = g_fB2[i];
        if (tid < 64) {
            muS[tid] = g_mu[(b << 6) + tid];
            rstdS[tid] = g_rstd[(b << 6) + tid];
        }
        if (tid < 128) {
            biasH[tid] = b_shared[tid];
            biasGB[tid] = (tid < 64) ? b_gamma[tid] : b_beta[tid - 64];
        }
        if (tid < 12) aS[tid] = g_a[tid];
    }
    __syncthreads();

    float areg[12];
#pragma unroll
    for (int j = 0; j < 12; j++) areg[j] = aS[j];

    // ---- separable FIR downsample into v[128 px][32 ch] (bf16), 4 channel groups ----
    for (int g = 0; g < 4; g++) {
        // load raw halo tile: 8 ch x 26 rows x 42 cols (zero padded)
        for (int e = tid; e < 8 * 26 * 42; e += 256) {
            int c = e / 1092;
            int rem = e - c * 1092;
            int r = rem / 42;
            int col = rem - r * 42;
            int gr = 2 * y0 - 5 + r;
            int gc = 2 * x0 - 5 + col;
            float val = 0.f;
            if ((unsigned)gr < 512u && (unsigned)gc < 512u)
                val = hm[(((size_t)b * CL + g * 8 + c) * HMimg + gr) * HMimg + gc];
            sraw[(c * 26 + r) * 44 + col] = val;
        }
        __syncthreads();
        // horizontal FIR (stride 2): 8 ch x 26 rows x 16 out-cols
        for (int e = tid; e < 8 * 26 * 16; e += 256) {
            int c = e / 416;
            int rem = e - c * 416;
            int r = rem >> 4;
            int ox = rem & 15;
            const float* rp = &sraw[(c * 26 + r) * 44 + 2 * ox];
            float acc = 0.f;
#pragma unroll
            for (int j = 0; j < 12; j++) acc += rp[j] * areg[j];
            sint[(c * 26 + r) * 16 + ox] = acc;
        }
        __syncthreads();
        // vertical FIR (stride 2): 128 px x 8 ch
        for (int e = tid; e < 1024; e += 256) {
            int px = e & 127;
            int c = e >> 7;
            int orow = px >> 4;
            int ox = px & 15;
            const float* ip = &sint[(c * 26 + 2 * orow) * 16 + ox];
            float acc = 0.f;
#pragma unroll
            for (int j = 0; j < 12; j++) acc += ip[j * 16] * areg[j];
            sv[px * 40 + g * 8 + c] = __float2bfloat16(acc);
        }
        __syncthreads();
    }

    // ---- GEMMs via bf16 mma.sync ----
    const int warp = tid >> 5;
    const int lane = tid & 31;
    const int gid = lane >> 2;
    const int tig = lane & 3;
    const int mbase = warp * 16;
    const int r16 = lane & 15;
    const int khalf = ((lane >> 4) << 3);  // 0 or 8

    unsigned sv_s = (unsigned)__cvta_generic_to_shared(sv);
    unsigned sh_s = (unsigned)__cvta_generic_to_shared(sh);
    unsigned vA = sv_s + ((mbase + r16) * 40 + khalf) * 2;
    unsigned hA = sh_s + ((mbase + r16) * 136 + khalf) * 2;

    // GEMM1: h[128px][128ch] = v[128][32] * Wshared^T, + bias, lrelu*gain -> sh (bf16)
    {
        unsigned A0[4], A1[4];
        ldsm4(A0, vA);
        ldsm4(A1, vA + 32);
        float acc[16][4];
#pragma unroll
        for (int nt = 0; nt < 16; nt++)
#pragma unroll
            for (int i = 0; i < 4; i++) acc[nt][i] = 0.f;
#pragma unroll
        for (int nt = 0; nt < 16; nt++) {
            uint2 b0 = *reinterpret_cast<const uint2*>(&sB1[(nt * 32 + lane) * 2]);
            uint2 b1 = *reinterpret_cast<const uint2*>(&sB1[((16 + nt) * 32 + lane) * 2]);
            mma_bf16(acc[nt], A0, b0.x, b0.y);
            mma_bf16(acc[nt], A1, b1.x, b1.y);
        }
        const int r0 = mbase + gid;
#pragma unroll
        for (int nt = 0; nt < 16; nt++) {
            int c0 = nt * 8 + tig * 2;
            float bb0 = biasH[c0], bb1 = biasH[c0 + 1];
            float v00 = acc[nt][0] + bb0, v01 = acc[nt][1] + bb1;
            float v10 = acc[nt][2] + bb0, v11 = acc[nt][3] + bb1;
            v00 = (v00 >= 0.f ? v00 : v00 * SLOPE) * GAINF;
            v01 = (v01 >= 0.f ? v01 : v01 * SLOPE) * GAINF;
            v10 = (v10 >= 0.f ? v10 : v10 * SLOPE) * GAINF;
            v11 = (v11 >= 0.f ? v11 : v11 * SLOPE) * GAINF;
            *reinterpret_cast<__nv_bfloat162*>(&sh[r0 * 136 + c0]) =
                __floats2bfloat162_rn(v00, v01);
            *reinterpret_cast<__nv_bfloat162*>(&sh[(r0 + 8) * 136 + c0]) =
                __floats2bfloat162_rn(v10, v11);
        }
    }
    __syncwarp();  // warp-private rows of h: only intra-warp visibility needed

    // GEMM2: gb[128px][128] = h[128][128] * W2^T (+bias) -> sh (bf16, overwrites h)
    {
        float facc[16][4];
#pragma unroll
        for (int nt = 0; nt < 16; nt++)
#pragma unroll
            for (int i = 0; i < 4; i++) facc[nt][i] = 0.f;
#pragma unroll
        for (int kt = 0; kt < 8; kt++) {
            unsigned A[4];
            ldsm4(A, hA + kt * 32);
#pragma unroll
            for (int nt = 0; nt < 16; nt++) {
                uint2 bb = *reinterpret_cast<const uint2*>(&sB2[((kt * 16 + nt) * 32 + lane) * 2]);
                mma_bf16(facc[nt], A, bb.x, bb.y);
            }
        }
        __syncwarp();
        const int r0 = mbase + gid;
#pragma unroll
        for (int nt = 0; nt < 16; nt++) {
            int c0 = nt * 8 + tig * 2;
            float bb0 = biasGB[c0], bb1 = biasGB[c0 + 1];
            *reinterpret_cast<__nv_bfloat162*>(&sh[r0 * 136 + c0]) =
                __floats2bfloat162_rn(facc[nt][0] + bb0, facc[nt][1] + bb1);
            *reinterpret_cast<__nv_bfloat162*>(&sh[(r0 + 8) * 136 + c0]) =
                __floats2bfloat162_rn(facc[nt][2] + bb0, facc[nt][3] + bb1);
        }
    }
    __syncthreads();

    // ---- epilogue: instance-norm modulate x, write out ----
    {
        const int p = tid & 127;
        const int chalf = tid >> 7;  // 0/1
        const int gy = y0 + (p >> 4);
        const int gx = x0 + (p & 15);
        const size_t base = ((size_t)b * CN) * 65536 + (size_t)gy * Himg + gx;
        const float* xp = x + base;
        float* op = out + base;
#pragma unroll 4
        for (int c = chalf; c < CN; c += 2) {
            float gamma = __bfloat162float(sh[p * 136 + c]);
            float beta = __bfloat162float(sh[p * 136 + 64 + c]);
            float xv = xp[(size_t)c * 65536];
            float xn = (xv - muS[c]) * rstdS[c];
            op[(size_t)c * 65536] = xn * (1.f + gamma) + beta + 0.1f * xv;
        }
    }
}

extern "C" void kernel_launch(void* const* d_in, const int* in_sizes, int n_in,
                              void* d_out, int out_size) {
    (void)in_sizes; (void)n_in; (void)out_size;
    const float* x        = (const float*)d_in[0];
    const float* hm       = (const float*)d_in[1];
    const float* F        = (const float*)d_in[2];
    const float* w_shared = (const float*)d_in[3];
    const float* b_shared = (const float*)d_in[4];
    const float* w_gamma  = (const float*)d_in[5];
    const float* b_gamma  = (const float*)d_in[6];
    const float* w_beta   = (const float*)d_in[7];
    const float* b_beta   = (const float*)d_in[8];
    float* out = (float*)d_out;

    prep_kernel<<<1, 256>>>(F, w_shared, w_gamma, w_beta);
    stats_kernel<<<512, 256>>>(x);
    cudaFuncSetAttribute(main_kernel, cudaFuncAttributeMaxDynamicSharedMemorySize, SMEM_TOTAL);
    dim3 grid(Himg / TW, Himg / TH, Bn);  // (16, 32, 8)
    main_kernel<<<grid, 256, SMEM_TOTAL>>>(x, hm, b_shared, b_gamma, b_beta, out);
}

// round 5
// speedup vs baseline: 1.0040x; 1.0040x over previous
#include <cuda_runtime.h>
#include <cuda_bf16.h>
#include <cstdint>

#define Bn 8
#define CN 64
#define CL 32
#define CH 128
#define Himg 256
#define HMimg 512
#define SLOPE 0.2f
#define GAINF 1.4142135623730951f
#define EPSV 1e-5f

// tile: 8 rows x 16 cols = 128 pixels per block
#define TH 8
#define TW 16

// smem layout (bytes) for gemm kernel
#define OFF_V 0              // 128*40 bf16 = 10240
#define OFF_REGION 10240     // union: sh[128][136] bf16 (34816) | raw(36608)+interm(13312)
#define OFF_RAW OFF_REGION
#define OFF_INT (OFF_REGION + 36608)
#define SMEM_TOTAL (OFF_REGION + 49920)   // 60160

__device__ float g_a[12];
__device__ uint2 g_fB1[1024];   // [kt2][nt16][lane32] -> (pair0,pair1) bf16x2
__device__ uint2 g_fB2[4096];   // [kt8][nt16][lane32] -> (pair0,pair1) bf16x2
__device__ unsigned g_gb[(size_t)Bn * CN * Himg * Himg];  // packed (gamma,beta) bf16x2

static __device__ __forceinline__ unsigned pack_bf16x2(float a, float b) {
    __nv_bfloat162 t = __floats2bfloat162_rn(a, b);
    return *reinterpret_cast<unsigned*>(&t);
}

// ---------------- prep: filter factorization + weight fragments ----------------
__global__ void prep_kernel(const float* __restrict__ F,
                            const float* __restrict__ w_shared,
                            const float* __restrict__ w_gamma,
                            const float* __restrict__ w_beta) {
    int tid = threadIdx.x;
    // F = outer(g,g); flipped 1D filter a[i] = g[11-i] = F[11-i][5]/sqrt(F[5][5])
    if (tid < 12) {
        g_a[tid] = F[(11 - tid) * 12 + 5] * rsqrtf(F[5 * 12 + 5]);
    }
    unsigned* B1 = reinterpret_cast<unsigned*>(g_fB1);
    for (int idx = tid; idx < 2048; idx += blockDim.x) {
        int pair = idx & 1;
        int lane = (idx >> 1) & 31;
        int nt = (idx >> 6) & 15;
        int kt = idx >> 10;
        int gid = lane >> 2, tig = lane & 3;
        int n = nt * 8 + gid;
        int k = kt * 16 + tig * 2 + pair * 8;
        B1[idx] = pack_bf16x2(w_shared[n * CL + k], w_shared[n * CL + k + 1]);
    }
    unsigned* B2 = reinterpret_cast<unsigned*>(g_fB2);
    for (int idx = tid; idx < 8192; idx += blockDim.x) {
        int pair = idx & 1;
        int lane = (idx >> 1) & 31;
        int nt = (idx >> 6) & 15;
        int kt = idx >> 10;
        int gid = lane >> 2, tig = lane & 3;
        int n = nt * 8 + gid;
        int k = kt * 16 + tig * 2 + pair * 8;
        float v0, v1;
        if (n < 64) { v0 = w_gamma[n * CH + k]; v1 = w_gamma[n * CH + k + 1]; }
        else        { v0 = w_beta[(n - 64) * CH + k]; v1 = w_beta[(n - 64) * CH + k + 1]; }
        B2[idx] = pack_bf16x2(v0, v1);
    }
}

// ---------------- mma helpers ----------------
static __device__ __forceinline__ void ldsm4(unsigned r[4], unsigned addr) {
    asm volatile("ldmatrix.sync.aligned.m8n8.x4.shared.b16 {%0,%1,%2,%3}, [%4];"
                 : "=r"(r[0]), "=r"(r[1]), "=r"(r[2]), "=r"(r[3])
                 : "r"(addr) : "memory");
}
static __device__ __forceinline__ void mma_bf16(float c[4], const unsigned a[4],
                                                unsigned b0, unsigned b1) {
    asm("mma.sync.aligned.m16n8k16.row.col.f32.bf16.bf16.f32 "
        "{%0,%1,%2,%3}, {%4,%5,%6,%7}, {%8,%9}, {%0,%1,%2,%3};"
        : "+f"(c[0]), "+f"(c[1]), "+f"(c[2]), "+f"(c[3])
        : "r"(a[0]), "r"(a[1]), "r"(a[2]), "r"(a[3]), "r"(b0), "r"(b1));
}

// ---------------- FIR + GEMM1 + GEMM2 -> packed gamma/beta ----------------
__global__ void __launch_bounds__(256, 2)
gemm_kernel(const float* __restrict__ hm,
            const float* __restrict__ b_shared,
            const float* __restrict__ b_gamma,
            const float* __restrict__ b_beta) {
    extern __shared__ char smem[];
    __nv_bfloat16* sv = reinterpret_cast<__nv_bfloat16*>(smem + OFF_V);      // [128][40]
    __nv_bfloat16* sh = reinterpret_cast<__nv_bfloat16*>(smem + OFF_REGION); // [128][136]
    float* sraw = reinterpret_cast<float*>(smem + OFF_RAW);                  // [8][26][44]
    float* sint = reinterpret_cast<float*>(smem + OFF_INT);                  // [8][26][16]

    const int tid = threadIdx.x;
    const int b = blockIdx.z;
    const int x0 = blockIdx.x * TW;
    const int y0 = blockIdx.y * TH;

    float areg[12];
#pragma unroll
    for (int j = 0; j < 12; j++) areg[j] = __ldg(&g_a[j]);

    // ---- separable FIR downsample into v[128 px][32 ch] (bf16), 4 channel groups ----
    for (int g = 0; g < 4; g++) {
        // load raw halo tile: 8 ch x 26 rows x 42 cols (zero padded)
        for (int e = tid; e < 8 * 26 * 42; e += 256) {
            int c = e / 1092;
            int rem = e - c * 1092;
            int r = rem / 42;
            int col = rem - r * 42;
            int gr = 2 * y0 - 5 + r;
            int gc = 2 * x0 - 5 + col;
            float val = 0.f;
            if ((unsigned)gr < 512u && (unsigned)gc < 512u)
                val = __ldg(&hm[(((size_t)b * CL + g * 8 + c) * HMimg + gr) * HMimg + gc]);
            sraw[(c * 26 + r) * 44 + col] = val;
        }
        __syncthreads();
        // horizontal FIR (stride 2): 8 ch x 26 rows x 16 out-cols
#pragma unroll 2
        for (int e = tid; e < 8 * 26 * 16; e += 256) {
            int c = e / 416;
            int rem = e - c * 416;
            int r = rem >> 4;
            int ox = rem & 15;
            const float* rp = &sraw[(c * 26 + r) * 44 + 2 * ox];
            // two 6-tap sub-chains to halve the FMA dependency depth
            float a0 = 0.f, a1 = 0.f;
#pragma unroll
            for (int j = 0; j < 6; j++) { a0 += rp[j] * areg[j]; a1 += rp[j + 6] * areg[j + 6]; }
            sint[(c * 26 + r) * 16 + ox] = a0 + a1;
        }
        __syncthreads();
        // vertical FIR (stride 2): 128 px x 8 ch
#pragma unroll 2
        for (int e = tid; e < 1024; e += 256) {
            int px = e & 127;
            int c = e >> 7;
            int orow = px >> 4;
            int ox = px & 15;
            const float* ip = &sint[(c * 26 + 2 * orow) * 16 + ox];
            float a0 = 0.f, a1 = 0.f;
#pragma unroll
            for (int j = 0; j < 6; j++) { a0 += ip[j * 16] * areg[j]; a1 += ip[(j + 6) * 16] * areg[j + 6]; }
            sv[px * 40 + g * 8 + c] = __float2bfloat16(a0 + a1);
        }
        __syncthreads();
    }

    // ---- GEMMs via bf16 mma.sync ----
    const int warp = tid >> 5;
    const int lane = tid & 31;
    const int gid = lane >> 2;
    const int tig = lane & 3;
    const int mbase = warp * 16;
    const int r16 = lane & 15;
    const int khalf = ((lane >> 4) << 3);  // 0 or 8

    unsigned sv_s = (unsigned)__cvta_generic_to_shared(sv);
    unsigned sh_s = (unsigned)__cvta_generic_to_shared(sh);
    unsigned vA = sv_s + ((mbase + r16) * 40 + khalf) * 2;
    unsigned hA = sh_s + ((mbase + r16) * 136 + khalf) * 2;

    // GEMM1: h[128px][128ch] = v[128][32] * Wshared^T, + bias, lrelu*gain -> sh (bf16)
    {
        unsigned A0[4], A1[4];
        ldsm4(A0, vA);
        ldsm4(A1, vA + 32);
        float acc[16][4];
#pragma unroll
        for (int nt = 0; nt < 16; nt++)
#pragma unroll
            for (int i = 0; i < 4; i++) acc[nt][i] = 0.f;
#pragma unroll
        for (int nt = 0; nt < 16; nt++) {
            uint2 b0 = __ldg(&g_fB1[nt * 32 + lane]);
            uint2 b1 = __ldg(&g_fB1[(16 + nt) * 32 + lane]);
            mma_bf16(acc[nt], A0, b0.x, b0.y);
            mma_bf16(acc[nt], A1, b1.x, b1.y);
        }
        const int r0 = mbase + gid;
#pragma unroll
        for (int nt = 0; nt < 16; nt++) {
            int c0 = nt * 8 + tig * 2;
            float bb0 = __ldg(&b_shared[c0]), bb1 = __ldg(&b_shared[c0 + 1]);
            float v00 = acc[nt][0] + bb0, v01 = acc[nt][1] + bb1;
            float v10 = acc[nt][2] + bb0, v11 = acc[nt][3] + bb1;
            v00 = (v00 >= 0.f ? v00 : v00 * SLOPE) * GAINF;
            v01 = (v01 >= 0.f ? v01 : v01 * SLOPE) * GAINF;
            v10 = (v10 >= 0.f ? v10 : v10 * SLOPE) * GAINF;
            v11 = (v11 >= 0.f ? v11 : v11 * SLOPE) * GAINF;
            *reinterpret_cast<__nv_bfloat162*>(&sh[r0 * 136 + c0]) =
                __floats2bfloat162_rn(v00, v01);
            *reinterpret_cast<__nv_bfloat162*>(&sh[(r0 + 8) * 136 + c0]) =
                __floats2bfloat162_rn(v10, v11);
        }
    }
    __syncwarp();  // warp-private rows of h: only intra-warp visibility needed

    // GEMM2: gb[128px][128] = h[128][128] * W2^T (+bias) -> sh (bf16, overwrites h)
    {
        float facc[16][4];
#pragma unroll
        for (int nt = 0; nt < 16; nt++)
#pragma unroll
            for (int i = 0; i < 4; i++) facc[nt][i] = 0.f;
#pragma unroll
        for (int kt = 0; kt < 8; kt++) {
            unsigned A[4];
            ldsm4(A, hA + kt * 32);
#pragma unroll
            for (int nt = 0; nt < 16; nt++) {
                uint2 bb = __ldg(&g_fB2[(kt * 16 + nt) * 32 + lane]);
                mma_bf16(facc[nt], A, bb.x, bb.y);
            }
        }
        __syncwarp();
        const int r0 = mbase + gid;
#pragma unroll
        for (int nt = 0; nt < 16; nt++) {
            int c0 = nt * 8 + tig * 2;
            float bb0 = (c0 < 64) ? __ldg(&b_gamma[c0]) : __ldg(&b_beta[c0 - 64]);
            float bb1 = (c0 + 1 < 64) ? __ldg(&b_gamma[c0 + 1]) : __ldg(&b_beta[c0 + 1 - 64]);
            *reinterpret_cast<__nv_bfloat162*>(&sh[r0 * 136 + c0]) =
                __floats2bfloat162_rn(facc[nt][0] + bb0, facc[nt][1] + bb1);
            *reinterpret_cast<__nv_bfloat162*>(&sh[(r0 + 8) * 136 + c0]) =
                __floats2bfloat162_rn(facc[nt][2] + bb0, facc[nt][3] + bb1);
        }
    }
    __syncthreads();

    // ---- write packed (gamma,beta) bf16x2 planes, channel-major, coalesced ----
    {
#pragma unroll 4
        for (int e = tid; e < 8192; e += 256) {
            int c = e >> 7;        // 0..63
            int px = e & 127;      // lanes cover consecutive px for fixed c
            float gamma = __bfloat162float(sh[px * 136 + c]);
            float beta  = __bfloat162float(sh[px * 136 + 64 + c]);
            int gy = y0 + (px >> 4);
            int gx = x0 + (px & 15);
            g_gb[(((size_t)b * CN + c) << 16) + gy * Himg + gx] = pack_bf16x2(gamma, beta);
        }
    }
}

// ---------------- fused instance-norm stats + apply (one block per (b,c) plane) ----------------
__global__ void __launch_bounds__(512, 2)
norm_apply_kernel(const float* __restrict__ x, float* __restrict__ out) {
    const int bc = blockIdx.x;
    const int tid = threadIdx.x;
    const float4* xp = reinterpret_cast<const float4*>(x + (size_t)bc * 65536);
    float4* op = reinterpret_cast<float4*>(out + (size_t)bc * 65536);
    const uint4* gbp = reinterpret_cast<const uint4*>(g_gb + ((size_t)bc << 16));

    // pass 1: stats over 64K elements (16384 float4)
    float s = 0.f, q = 0.f;
#pragma unroll 8
    for (int i = tid; i < 16384; i += 512) {
        float4 v = xp[i];
        s += (v.x + v.y) + (v.z + v.w);
        q += v.x * v.x + v.y * v.y + v.z * v.z + v.w * v.w;
    }
#pragma unroll
    for (int o = 16; o > 0; o >>= 1) {
        s += __shfl_down_sync(0xffffffffu, s, o);
        q += __shfl_down_sync(0xffffffffu, q, o);
    }
    __shared__ float ws[16], wq[16], stat[2];
    int w = tid >> 5;
    if ((tid & 31) == 0) { ws[w] = s; wq[w] = q; }
    __syncthreads();
    if (tid == 0) {
        float S = 0.f, Q = 0.f;
#pragma unroll
        for (int i = 0; i < 16; i++) { S += ws[i]; Q += wq[i]; }
        float mu = S * (1.f / 65536.f);
        float var = Q * (1.f / 65536.f) - mu * mu;
        stat[0] = mu;
        stat[1] = rsqrtf(var + EPSV);
    }
    __syncthreads();
    const float mu = stat[0];
    const float rstd = stat[1];

    // pass 2: apply (x mostly L2-resident from pass 1)
#pragma unroll 4
    for (int i = tid; i < 16384; i += 512) {
        float4 v = xp[i];
        uint4 g = gbp[i];
        float4 r;
        {
            __nv_bfloat162 p = *reinterpret_cast<__nv_bfloat162*>(&g.x);
            float xn = (v.x - mu) * rstd;
            r.x = xn * (1.f + __bfloat162float(p.x)) + __bfloat162float(p.y) + 0.1f * v.x;
        }
        {
            __nv_bfloat162 p = *reinterpret_cast<__nv_bfloat162*>(&g.y);
            float xn = (v.y - mu) * rstd;
            r.y = xn * (1.f + __bfloat162float(p.x)) + __bfloat162float(p.y) + 0.1f * v.y;
        }
        {
            __nv_bfloat162 p = *reinterpret_cast<__nv_bfloat162*>(&g.z);
            float xn = (v.z - mu) * rstd;
            r.z = xn * (1.f + __bfloat162float(p.x)) + __bfloat162float(p.y) + 0.1f * v.z;
        }
        {
            __nv_bfloat162 p = *reinterpret_cast<__nv_bfloat162*>(&g.w);
            float xn = (v.w - mu) * rstd;
            r.w = xn * (1.f + __bfloat162float(p.x)) + __bfloat162float(p.y) + 0.1f * v.w;
        }
        op[i] = r;
    }
}

extern "C" void kernel_launch(void* const* d_in, const int* in_sizes, int n_in,
                              void* d_out, int out_size) {
    (void)in_sizes; (void)n_in; (void)out_size;
    const float* x        = (const float*)d_in[0];
    const float* hm       = (const float*)d_in[1];
    const float* F        = (const float*)d_in[2];
    const float* w_shared = (const float*)d_in[3];
    const float* b_shared = (const float*)d_in[4];
    const float* w_gamma  = (const float*)d_in[5];
    const float* b_gamma  = (const float*)d_in[6];
    const float* w_beta   = (const float*)d_in[7];
    const float* b_beta   = (const float*)d_in[8];
    float* out = (float*)d_out;

    prep_kernel<<<1, 256>>>(F, w_shared, w_gamma, w_beta);
    cudaFuncSetAttribute(gemm_kernel, cudaFuncAttributeMaxDynamicSharedMemorySize, SMEM_TOTAL);
    dim3 grid(Himg / TW, Himg / TH, Bn);  // (16, 32, 8)
    gemm_kernel<<<grid, 256, SMEM_TOTAL>>>(hm, b_shared, b_gamma, b_beta);
    norm_apply_kernel<<<Bn * CN, 512>>>(x, out);
}

// round 6
// speedup vs baseline: 1.4783x; 1.4725x over previous
#include <cuda_runtime.h>
#include <cuda_bf16.h>
#include <cstdint>

#define Bn 8
#define CN 64
#define CL 32
#define CH 128
#define Himg 256
#define HMimg 512
#define SLOPE 0.2f
#define GAINF 1.4142135623730951f
#define EPSV 1e-5f

__device__ float g_a[12];
__device__ uint2 g_fB1[1024];   // [kt2][nt16][lane32] -> (pair0,pair1) bf16x2
__device__ uint2 g_fB2[4096];   // [kt8][nt16][lane32] -> (pair0,pair1) bf16x2
__device__ __nv_bfloat16 g_v[(size_t)Bn * 65536 * CL];  // [b][px][32] downsampled
__device__ unsigned g_gb[(size_t)Bn * CN * 65536];      // packed (gamma,beta) bf16x2

static __device__ __forceinline__ unsigned pack_bf16x2(float a, float b) {
    __nv_bfloat162 t = __floats2bfloat162_rn(a, b);
    return *reinterpret_cast<unsigned*>(&t);
}

// ---------------- prep: filter factorization + weight fragments ----------------
__global__ void prep_kernel(const float* __restrict__ F,
                            const float* __restrict__ w_shared,
                            const float* __restrict__ w_gamma,
                            const float* __restrict__ w_beta) {
    int tid = threadIdx.x;
    // F = outer(g,g); flipped 1D filter a[i] = g[11-i] = F[11-i][5]/sqrt(F[5][5])
    if (tid < 12) {
        g_a[tid] = F[(11 - tid) * 12 + 5] * rsqrtf(F[5 * 12 + 5]);
    }
    unsigned* B1 = reinterpret_cast<unsigned*>(g_fB1);
    for (int idx = tid; idx < 2048; idx += blockDim.x) {
        int pair = idx & 1;
        int lane = (idx >> 1) & 31;
        int nt = (idx >> 6) & 15;
        int kt = idx >> 10;
        int gid = lane >> 2, tig = lane & 3;
        int n = nt * 8 + gid;
        int k = kt * 16 + tig * 2 + pair * 8;
        B1[idx] = pack_bf16x2(w_shared[n * CL + k], w_shared[n * CL + k + 1]);
    }
    unsigned* B2 = reinterpret_cast<unsigned*>(g_fB2);
    for (int idx = tid; idx < 8192; idx += blockDim.x) {
        int pair = idx & 1;
        int lane = (idx >> 1) & 31;
        int nt = (idx >> 6) & 15;
        int kt = idx >> 10;
        int gid = lane >> 2, tig = lane & 3;
        int n = nt * 8 + gid;
        int k = kt * 16 + tig * 2 + pair * 8;
        float v0, v1;
        if (n < 64) { v0 = w_gamma[n * CH + k]; v1 = w_gamma[n * CH + k + 1]; }
        else        { v0 = w_beta[(n - 64) * CH + k]; v1 = w_beta[(n - 64) * CH + k + 1]; }
        B2[idx] = pack_bf16x2(v0, v1);
    }
}

// ---------------- FIR downsample: 16x16 out-tile, 4 channels per block ----------------
// grid (16, 16, 64): x=col-tile, y=row-tile, z = b*8 + chgroup
__global__ void __launch_bounds__(256)
fir_kernel(const float* __restrict__ hm) {
    __shared__ float sraw[4 * 42 * 44];  // (c*42+r)*44+col
    __shared__ float sint[4 * 42 * 16];

    const int tid = threadIdx.x;
    const int x0 = blockIdx.x * 16;
    const int y0 = blockIdx.y * 16;
    const int b = blockIdx.z >> 3;
    const int g = blockIdx.z & 7;

    float areg[12];
#pragma unroll
    for (int j = 0; j < 12; j++) areg[j] = __ldg(&g_a[j]);

    // load raw halo tile: 4 ch x 42 rows x 42 cols (zero padded)
    const float* hmb = hm + ((size_t)(b * CL + g * 4)) * HMimg * HMimg;
    for (int e = tid; e < 4 * 42 * 42; e += 256) {
        int c = e / 1764;
        int rem = e - c * 1764;
        int r = rem / 42;
        int col = rem - r * 42;
        int gr = 2 * y0 - 5 + r;
        int gc = 2 * x0 - 5 + col;
        float val = 0.f;
        if ((unsigned)gr < 512u && (unsigned)gc < 512u)
            val = __ldg(hmb + (size_t)c * (HMimg * HMimg) + gr * HMimg + gc);
        sraw[(c * 42 + r) * 44 + col] = val;
    }
    __syncthreads();

    // horizontal FIR (stride 2): 4 ch x 42 rows x 16 out-cols
    for (int e = tid; e < 4 * 42 * 16; e += 256) {
        int c = e / 672;
        int rem = e - c * 672;
        int r = rem >> 4;
        int ox = rem & 15;
        const float* rp = &sraw[(c * 42 + r) * 44 + 2 * ox];
        float a0 = 0.f, a1 = 0.f;
#pragma unroll
        for (int j = 0; j < 6; j++) { a0 += rp[j] * areg[j]; a1 += rp[j + 6] * areg[j + 6]; }
        sint[(c * 42 + r) * 16 + ox] = a0 + a1;
    }
    __syncthreads();

    // vertical FIR (stride 2): thread = one out pixel, all 4 channels
    {
        int orow = tid >> 4;
        int ox = tid & 15;
        float res[4];
#pragma unroll
        for (int c = 0; c < 4; c++) {
            const float* ip = &sint[(c * 42 + 2 * orow) * 16 + ox];
            float a0 = 0.f, a1 = 0.f;
#pragma unroll
            for (int j = 0; j < 6; j++) { a0 += ip[j * 16] * areg[j]; a1 += ip[(j + 6) * 16] * areg[j + 6]; }
            res[c] = a0 + a1;
        }
        size_t px = (size_t)(y0 + orow) * Himg + (x0 + ox);
        uint2 val;
        val.x = pack_bf16x2(res[0], res[1]);
        val.y = pack_bf16x2(res[2], res[3]);
        *reinterpret_cast<uint2*>(&g_v[((size_t)b * 65536 + px) * CL + g * 4]) = val;
    }
}

// ---------------- mma helpers ----------------
static __device__ __forceinline__ void ldsm4(unsigned r[4], unsigned addr) {
    asm volatile("ldmatrix.sync.aligned.m8n8.x4.shared.b16 {%0,%1,%2,%3}, [%4];"
                 : "=r"(r[0]), "=r"(r[1]), "=r"(r[2]), "=r"(r[3])
                 : "r"(addr) : "memory");
}
static __device__ __forceinline__ void mma_bf16(float c[4], const unsigned a[4],
                                                unsigned b0, unsigned b1) {
    asm("mma.sync.aligned.m16n8k16.row.col.f32.bf16.bf16.f32 "
        "{%0,%1,%2,%3}, {%4,%5,%6,%7}, {%8,%9}, {%0,%1,%2,%3};"
        : "+f"(c[0]), "+f"(c[1]), "+f"(c[2]), "+f"(c[3])
        : "r"(a[0]), "r"(a[1]), "r"(a[2]), "r"(a[3]), "r"(b0), "r"(b1));
}

// ---------------- GEMM1 + GEMM2 -> packed gamma/beta ----------------
// grid (512, 8): 128 consecutive px per block. 8 warps as 4(M) x 2(N).
__global__ void __launch_bounds__(256, 2)
gemm_kernel(const float* __restrict__ b_shared,
            const float* __restrict__ b_gamma,
            const float* __restrict__ b_beta) {
    __shared__ __nv_bfloat16 sh[128 * 136];      // also aliased as sv[128][40] during A-stage
    __nv_bfloat16* sv = sh;

    const int tid = threadIdx.x;
    const int lane = tid & 31;
    const int warp = tid >> 5;
    const int b = blockIdx.y;
    const int px0 = blockIdx.x * 128;

    // stage A: v[px0..px0+128][0..32] bf16 -> sv[128][40]
    {
        const uint4* src = reinterpret_cast<const uint4*>(g_v + ((size_t)b * 65536 + px0) * CL);
        for (int i = tid; i < 512; i += 256) {
            int row = i >> 2, q = i & 3;
            *reinterpret_cast<uint4*>(&sv[row * 40 + q * 8]) = src[row * 4 + q];
        }
    }
    __syncthreads();

    const int mrow = warp & 3;            // 0..3 -> M offset 32*mrow
    const int ncol = warp >> 2;           // 0..1 -> N offset 64*ncol
    const int mbase = mrow * 32;
    const int gid = lane >> 2, tig = lane & 3;
    const int r16 = lane & 15;
    const int khalf = (lane >> 4) << 3;

    unsigned sbase = (unsigned)__cvta_generic_to_shared(sh);

    // ---- GEMM1: load A fragments up-front (sv will be overwritten by sh) ----
    unsigned A1[2][2][4];
#pragma unroll
    for (int mt = 0; mt < 2; mt++)
#pragma unroll
        for (int kt = 0; kt < 2; kt++)
            ldsm4(A1[mt][kt], sbase + ((mbase + mt * 16 + r16) * 40 + khalf + kt * 16) * 2);
    __syncthreads();

    {
        float acc[2][8][4];
#pragma unroll
        for (int mt = 0; mt < 2; mt++)
#pragma unroll
            for (int nt = 0; nt < 8; nt++)
#pragma unroll
                for (int i = 0; i < 4; i++) acc[mt][nt][i] = 0.f;
#pragma unroll
        for (int kt = 0; kt < 2; kt++)
#pragma unroll
            for (int nt = 0; nt < 8; nt++) {
                uint2 bb = __ldg(&g_fB1[(kt * 16 + ncol * 8 + nt) * 32 + lane]);
                mma_bf16(acc[0][nt], A1[0][kt], bb.x, bb.y);
                mma_bf16(acc[1][nt], A1[1][kt], bb.x, bb.y);
            }
        // epilogue1: bias + lrelu*gain -> sh (bf16)
#pragma unroll
        for (int mt = 0; mt < 2; mt++) {
            const int r0 = mbase + mt * 16 + gid;
#pragma unroll
            for (int nt = 0; nt < 8; nt++) {
                int c0 = (ncol * 8 + nt) * 8 + tig * 2;
                float bb0 = __ldg(&b_shared[c0]), bb1 = __ldg(&b_shared[c0 + 1]);
                float v00 = acc[mt][nt][0] + bb0, v01 = acc[mt][nt][1] + bb1;
                float v10 = acc[mt][nt][2] + bb0, v11 = acc[mt][nt][3] + bb1;
                v00 = (v00 >= 0.f ? v00 : v00 * SLOPE) * GAINF;
                v01 = (v01 >= 0.f ? v01 : v01 * SLOPE) * GAINF;
                v10 = (v10 >= 0.f ? v10 : v10 * SLOPE) * GAINF;
                v11 = (v11 >= 0.f ? v11 : v11 * SLOPE) * GAINF;
                *reinterpret_cast<__nv_bfloat162*>(&sh[r0 * 136 + c0]) =
                    __floats2bfloat162_rn(v00, v01);
                *reinterpret_cast<__nv_bfloat162*>(&sh[(r0 + 8) * 136 + c0]) =
                    __floats2bfloat162_rn(v10, v11);
            }
        }
    }
    __syncthreads();

    // ---- GEMM2: gb = h * W2^T ----
    float acc2[2][8][4];
#pragma unroll
    for (int mt = 0; mt < 2; mt++)
#pragma unroll
        for (int nt = 0; nt < 8; nt++)
#pragma unroll
            for (int i = 0; i < 4; i++) acc2[mt][nt][i] = 0.f;
#pragma unroll
    for (int kt = 0; kt < 8; kt++) {
        unsigned A[2][4];
        ldsm4(A[0], sbase + ((mbase + r16) * 136 + khalf + kt * 16) * 2);
        ldsm4(A[1], sbase + ((mbase + 16 + r16) * 136 + khalf + kt * 16) * 2);
#pragma unroll
        for (int nt = 0; nt < 8; nt++) {
            uint2 bb = __ldg(&g_fB2[(kt * 16 + ncol * 8 + nt) * 32 + lane]);
            mma_bf16(acc2[0][nt], A[0], bb.x, bb.y);
            mma_bf16(acc2[1][nt], A[1], bb.x, bb.y);
        }
    }
    __syncthreads();  // all ldsm reads of sh complete before overwrite

    // epilogue2: + bias -> sh (bf16)
#pragma unroll
    for (int mt = 0; mt < 2; mt++) {
        const int r0 = mbase + mt * 16 + gid;
#pragma unroll
        for (int nt = 0; nt < 8; nt++) {
            int n0 = (ncol * 8 + nt) * 8 + tig * 2;
            float bb0 = (n0 < 64) ? __ldg(&b_gamma[n0]) : __ldg(&b_beta[n0 - 64]);
            float bb1 = (n0 + 1 < 64) ? __ldg(&b_gamma[n0 + 1]) : __ldg(&b_beta[n0 + 1 - 64]);
            *reinterpret_cast<__nv_bfloat162*>(&sh[r0 * 136 + n0]) =
                __floats2bfloat162_rn(acc2[mt][nt][0] + bb0, acc2[mt][nt][1] + bb1);
            *reinterpret_cast<__nv_bfloat162*>(&sh[(r0 + 8) * 136 + n0]) =
                __floats2bfloat162_rn(acc2[mt][nt][2] + bb0, acc2[mt][nt][3] + bb1);
        }
    }
    __syncthreads();

    // store packed (gamma,beta), coalesced per channel plane
    {
        unsigned* gbp = g_gb + (((size_t)b * CN) << 16) + px0;
#pragma unroll 4
        for (int e = tid; e < 8192; e += 256) {
            int c = e >> 7;
            int px = e & 127;
            float gamma = __bfloat162float(sh[px * 136 + c]);
            float beta  = __bfloat162float(sh[px * 136 + 64 + c]);
            gbp[((size_t)c << 16) + px] = pack_bf16x2(gamma, beta);
        }
    }
}

// ---------------- fused instance-norm stats + apply (one block per (b,c) plane) ----------------
__global__ void __launch_bounds__(512, 2)
norm_apply_kernel(const float* __restrict__ x, float* __restrict__ out) {
    const int bc = blockIdx.x;
    const int tid = threadIdx.x;
    const float4* xp = reinterpret_cast<const float4*>(x + (size_t)bc * 65536);
    float4* op = reinterpret_cast<float4*>(out + (size_t)bc * 65536);
    const uint4* gbp = reinterpret_cast<const uint4*>(g_gb + ((size_t)bc << 16));

    float s = 0.f, q = 0.f;
#pragma unroll 8
    for (int i = tid; i < 16384; i += 512) {
        float4 v = xp[i];
        s += (v.x + v.y) + (v.z + v.w);
        q += v.x * v.x + v.y * v.y + v.z * v.z + v.w * v.w;
    }
#pragma unroll
    for (int o = 16; o > 0; o >>= 1) {
        s += __shfl_down_sync(0xffffffffu, s, o);
        q += __shfl_down_sync(0xffffffffu, q, o);
    }
    __shared__ float ws[16], wq[16], stat[2];
    int w = tid >> 5;
    if ((tid & 31) == 0) { ws[w] = s; wq[w] = q; }
    __syncthreads();
    if (tid == 0) {
        float S = 0.f, Q = 0.f;
#pragma unroll
        for (int i = 0; i < 16; i++) { S += ws[i]; Q += wq[i]; }
        float mu = S * (1.f / 65536.f);
        float var = Q * (1.f / 65536.f) - mu * mu;
        stat[0] = mu;
        stat[1] = rsqrtf(var + EPSV);
    }
    __syncthreads();
    const float mu = stat[0];
    const float rstd = stat[1];

#pragma unroll 4
    for (int i = tid; i < 16384; i += 512) {
        float4 v = xp[i];
        uint4 g = gbp[i];
        float4 r;
        {
            __nv_bfloat162 p = *reinterpret_cast<__nv_bfloat162*>(&g.x);
            float xn = (v.x - mu) * rstd;
            r.x = xn * (1.f + __bfloat162float(p.x)) + __bfloat162float(p.y) + 0.1f * v.x;
        }
        {
            __nv_bfloat162 p = *reinterpret_cast<__nv_bfloat162*>(&g.y);
            float xn = (v.y - mu) * rstd;
            r.y = xn * (1.f + __bfloat162float(p.x)) + __bfloat162float(p.y) + 0.1f * v.y;
        }
        {
            __nv_bfloat162 p = *reinterpret_cast<__nv_bfloat162*>(&g.z);
            float xn = (v.z - mu) * rstd;
            r.z = xn * (1.f + __bfloat162float(p.x)) + __bfloat162float(p.y) + 0.1f * v.z;
        }
        {
            __nv_bfloat162 p = *reinterpret_cast<__nv_bfloat162*>(&g.w);
            float xn = (v.w - mu) * rstd;
            r.w = xn * (1.f + __bfloat162float(p.x)) + __bfloat162float(p.y) + 0.1f * v.w;
        }
        op[i] = r;
    }
}

extern "C" void kernel_launch(void* const* d_in, const int* in_sizes, int n_in,
                              void* d_out, int out_size) {
    (void)in_sizes; (void)n_in; (void)out_size;
    const float* x        = (const float*)d_in[0];
    const float* hm       = (const float*)d_in[1];
    const float* F        = (const float*)d_in[2];
    const float* w_shared = (const float*)d_in[3];
    const float* b_shared = (const float*)d_in[4];
    const float* w_gamma  = (const float*)d_in[5];
    const float* b_gamma  = (const float*)d_in[6];
    const float* w_beta   = (const float*)d_in[7];
    const float* b_beta   = (const float*)d_in[8];
    float* out = (float*)d_out;

    prep_kernel<<<1, 256>>>(F, w_shared, w_gamma, w_beta);
    dim3 fgrid(16, 16, 64);
    fir_kernel<<<fgrid, 256>>>(hm);
    dim3 ggrid(512, 8);
    gemm_kernel<<<ggrid, 256>>>(b_shared, b_gamma, b_beta);
    norm_apply_kernel<<<Bn * CN, 512>>>(x, out);
}

// round 7
// speedup vs baseline: 1.5741x; 1.0648x over previous
#include <cuda_runtime.h>
#include <cuda_bf16.h>
#include <cstdint>

#define Bn 8
#define CN 64
#define CL 32
#define CH 128
#define Himg 256
#define HMimg 512
#define SLOPE 0.2f
#define GAINF 1.4142135623730951f
#define EPSV 1e-5f

__device__ float g_a[12];
__device__ uint2 g_fB1[1024];   // [kt2][nt16][lane32] -> (pair0,pair1) bf16x2
__device__ uint2 g_fB2[4096];   // [kt8][nt16][lane32] -> (pair0,pair1) bf16x2
// layout: [b][chgroup(8)][px(65536)][4ch] bf16  (one uint2 per (px,group))
__device__ __nv_bfloat16 g_v[(size_t)Bn * 8 * 65536 * 4];
__device__ unsigned g_gb[(size_t)Bn * CN * 65536];      // packed (gamma,beta) bf16x2

static __device__ __forceinline__ unsigned pack_bf16x2(float a, float b) {
    __nv_bfloat162 t = __floats2bfloat162_rn(a, b);
    return *reinterpret_cast<unsigned*>(&t);
}

// ---------------- prep: filter factorization + weight fragments ----------------
__global__ void prep_kernel(const float* __restrict__ F,
                            const float* __restrict__ w_shared,
                            const float* __restrict__ w_gamma,
                            const float* __restrict__ w_beta) {
    int tid = threadIdx.x;
    // F = outer(g,g); flipped 1D filter a[i] = g[11-i] = F[11-i][5]/sqrt(F[5][5])
    if (tid < 12) {
        g_a[tid] = F[(11 - tid) * 12 + 5] * rsqrtf(F[5 * 12 + 5]);
    }
    unsigned* B1 = reinterpret_cast<unsigned*>(g_fB1);
    for (int idx = tid; idx < 2048; idx += blockDim.x) {
        int pair = idx & 1;
        int lane = (idx >> 1) & 31;
        int nt = (idx >> 6) & 15;
        int kt = idx >> 10;
        int gid = lane >> 2, tig = lane & 3;
        int n = nt * 8 + gid;
        int k = kt * 16 + tig * 2 + pair * 8;
        B1[idx] = pack_bf16x2(w_shared[n * CL + k], w_shared[n * CL + k + 1]);
    }
    unsigned* B2 = reinterpret_cast<unsigned*>(g_fB2);
    for (int idx = tid; idx < 8192; idx += blockDim.x) {
        int pair = idx & 1;
        int lane = (idx >> 1) & 31;
        int nt = (idx >> 6) & 15;
        int kt = idx >> 10;
        int gid = lane >> 2, tig = lane & 3;
        int n = nt * 8 + gid;
        int k = kt * 16 + tig * 2 + pair * 8;
        float v0, v1;
        if (n < 64) { v0 = w_gamma[n * CH + k]; v1 = w_gamma[n * CH + k + 1]; }
        else        { v0 = w_beta[(n - 64) * CH + k]; v1 = w_beta[(n - 64) * CH + k + 1]; }
        B2[idx] = pack_bf16x2(v0, v1);
    }
}

// ---------------- FIR downsample: 16x16 out-tile, 4 channels per block ----------------
// grid (16, 16, 64): x=col-tile, y=row-tile, z = b*8 + chgroup
__global__ void __launch_bounds__(256)
fir_kernel(const float* __restrict__ hm) {
    __shared__ float sraw[4 * 42 * 44];   // (c*42+r)*44+col   29568 B
    __shared__ float sint[4 * 42 * 16];   // (c*42+r)*16+ox    10752 B
    __shared__ float sres[4 * 16 * 16];   // (c*16+or)*16+ox    4096 B

    const int tid = threadIdx.x;
    const int x0 = blockIdx.x * 16;
    const int y0 = blockIdx.y * 16;
    const int b = blockIdx.z >> 3;
    const int g = blockIdx.z & 7;

    float areg[12];
#pragma unroll
    for (int j = 0; j < 12; j++) areg[j] = __ldg(&g_a[j]);

    // phase 1: load raw halo tile: 4 ch x 42 rows x 42 cols (zero padded)
    const float* hmb = hm + ((size_t)(b * CL + g * 4)) * HMimg * HMimg;
    for (int e = tid; e < 4 * 42 * 42; e += 256) {
        int c = e / 1764;
        int rem = e - c * 1764;
        int r = rem / 42;
        int col = rem - r * 42;
        int gr = 2 * y0 - 5 + r;
        int gc = 2 * x0 - 5 + col;
        float val = 0.f;
        if ((unsigned)gr < 512u && (unsigned)gc < 512u)
            val = __ldg(hmb + (size_t)c * (HMimg * HMimg) + gr * HMimg + gc);
        sraw[(c * 42 + r) * 44 + col] = val;
    }
    __syncthreads();

    // phase 2: horizontal FIR (stride 2), 4 outputs per thread via float4 reads
    // tasks: 4ch x 42rows x 4 quads = 672
    for (int t = tid; t < 672; t += 256) {
        int c = t / 168;
        int rem = t - c * 168;
        int r = rem >> 2;
        int oq = rem & 3;                        // quad: out cols oq*4 .. oq*4+3
        const float4* rp = reinterpret_cast<const float4*>(&sraw[(c * 42 + r) * 44 + oq * 8]);
        float w[20];
#pragma unroll
        for (int q = 0; q < 5; q++) {
            float4 v = rp[q];
            w[q * 4 + 0] = v.x; w[q * 4 + 1] = v.y; w[q * 4 + 2] = v.z; w[q * 4 + 3] = v.w;
        }
        float o[4];
#pragma unroll
        for (int q = 0; q < 4; q++) {
            float a0 = 0.f, a1 = 0.f;
#pragma unroll
            for (int j = 0; j < 6; j++) {
                a0 += w[2 * q + j] * areg[j];
                a1 += w[2 * q + 6 + j] * areg[j + 6];
            }
            o[q] = a0 + a1;
        }
        *reinterpret_cast<float4*>(&sint[(c * 42 + r) * 16 + oq * 4]) =
            make_float4(o[0], o[1], o[2], o[3]);
    }
    __syncthreads();

    // phase 3: vertical FIR (stride 2), 4 output-rows per thread (one column)
    {
        int c = tid >> 6;          // 0..3
        int rem = tid & 63;
        int og = rem >> 4;         // 0..3 -> out rows og*4 .. og*4+3
        int ox = rem & 15;
        const float* ip = &sint[(c * 42 + og * 8) * 16 + ox];
        float w[18];
#pragma unroll
        for (int j = 0; j < 18; j++) w[j] = ip[j * 16];
#pragma unroll
        for (int q = 0; q < 4; q++) {
            float a0 = 0.f, a1 = 0.f;
#pragma unroll
            for (int j = 0; j < 6; j++) {
                a0 += w[2 * q + j] * areg[j];
                a1 += w[2 * q + 6 + j] * areg[j + 6];
            }
            sres[(c * 16 + og * 4 + q) * 16 + ox] = a0 + a1;
        }
    }
    __syncthreads();

    // phase 4: pack 4 channels per pixel, coalesced store
    {
        int orow = tid >> 4;
        int ox = tid & 15;
        uint2 val;
        val.x = pack_bf16x2(sres[(0 * 16 + orow) * 16 + ox], sres[(1 * 16 + orow) * 16 + ox]);
        val.y = pack_bf16x2(sres[(2 * 16 + orow) * 16 + ox], sres[(3 * 16 + orow) * 16 + ox]);
        size_t px = (size_t)(y0 + orow) * Himg + (x0 + ox);
        reinterpret_cast<uint2*>(g_v)[((size_t)blockIdx.z << 16) + px] = val;
    }
}

// ---------------- mma helpers ----------------
static __device__ __forceinline__ void ldsm4(unsigned r[4], unsigned addr) {
    asm volatile("ldmatrix.sync.aligned.m8n8.x4.shared.b16 {%0,%1,%2,%3}, [%4];"
                 : "=r"(r[0]), "=r"(r[1]), "=r"(r[2]), "=r"(r[3])
                 : "r"(addr) : "memory");
}
static __device__ __forceinline__ void mma_bf16(float c[4], const unsigned a[4],
                                                unsigned b0, unsigned b1) {
    asm("mma.sync.aligned.m16n8k16.row.col.f32.bf16.bf16.f32 "
        "{%0,%1,%2,%3}, {%4,%5,%6,%7}, {%8,%9}, {%0,%1,%2,%3};"
        : "+f"(c[0]), "+f"(c[1]), "+f"(c[2]), "+f"(c[3])
        : "r"(a[0]), "r"(a[1]), "r"(a[2]), "r"(a[3]), "r"(b0), "r"(b1));
}

// ---------------- GEMM1 + GEMM2 -> packed gamma/beta ----------------
// grid (512, 8): 128 consecutive px per block. 8 warps as 4(M) x 2(N).
__global__ void __launch_bounds__(256, 2)
gemm_kernel(const float* __restrict__ b_shared,
            const float* __restrict__ b_gamma,
            const float* __restrict__ b_beta) {
    __shared__ __nv_bfloat16 sh[128 * 136];      // also aliased as sv[128][40] during A-stage
    __nv_bfloat16* sv = sh;

    const int tid = threadIdx.x;
    const int lane = tid & 31;
    const int warp = tid >> 5;
    const int b = blockIdx.y;
    const int px0 = blockIdx.x * 128;

    // stage A: v from [b][g][px][4] layout -> sv[128][40]
    {
        const uint2* src = reinterpret_cast<const uint2*>(g_v) + (((size_t)b * 8) << 16) + px0;
        for (int e = tid; e < 1024; e += 256) {
            int g = e >> 7, px = e & 127;
            uint2 v = __ldg(&src[((size_t)g << 16) + px]);
            *reinterpret_cast<uint2*>(&sv[px * 40 + g * 4]) = v;
        }
    }
    __syncthreads();

    const int mrow = warp & 3;            // 0..3 -> M offset 32*mrow
    const int ncol = warp >> 2;           // 0..1 -> N offset 64*ncol
    const int mbase = mrow * 32;
    const int gid = lane >> 2, tig = lane & 3;
    const int r16 = lane & 15;
    const int khalf = (lane >> 4) << 3;

    unsigned sbase = (unsigned)__cvta_generic_to_shared(sh);

    // ---- GEMM1: load A fragments up-front (sv will be overwritten by sh) ----
    unsigned A1[2][2][4];
#pragma unroll
    for (int mt = 0; mt < 2; mt++)
#pragma unroll
        for (int kt = 0; kt < 2; kt++)
            ldsm4(A1[mt][kt], sbase + ((mbase + mt * 16 + r16) * 40 + khalf + kt * 16) * 2);
    __syncthreads();

    {
        float acc[2][8][4];
#pragma unroll
        for (int mt = 0; mt < 2; mt++)
#pragma unroll
            for (int nt = 0; nt < 8; nt++)
#pragma unroll
                for (int i = 0; i < 4; i++) acc[mt][nt][i] = 0.f;
#pragma unroll
        for (int kt = 0; kt < 2; kt++)
#pragma unroll
            for (int nt = 0; nt < 8; nt++) {
                uint2 bb = __ldg(&g_fB1[(kt * 16 + ncol * 8 + nt) * 32 + lane]);
                mma_bf16(acc[0][nt], A1[0][kt], bb.x, bb.y);
                mma_bf16(acc[1][nt], A1[1][kt], bb.x, bb.y);
            }
        // epilogue1: bias + lrelu*gain -> sh (bf16)
#pragma unroll
        for (int mt = 0; mt < 2; mt++) {
            const int r0 = mbase + mt * 16 + gid;
#pragma unroll
            for (int nt = 0; nt < 8; nt++) {
                int c0 = (ncol * 8 + nt) * 8 + tig * 2;
                float bb0 = __ldg(&b_shared[c0]), bb1 = __ldg(&b_shared[c0 + 1]);
                float v00 = acc[mt][nt][0] + bb0, v01 = acc[mt][nt][1] + bb1;
                float v10 = acc[mt][nt][2] + bb0, v11 = acc[mt][nt][3] + bb1;
                v00 = (v00 >= 0.f ? v00 : v00 * SLOPE) * GAINF;
                v01 = (v01 >= 0.f ? v01 : v01 * SLOPE) * GAINF;
                v10 = (v10 >= 0.f ? v10 : v10 * SLOPE) * GAINF;
                v11 = (v11 >= 0.f ? v11 : v11 * SLOPE) * GAINF;
                *reinterpret_cast<__nv_bfloat162*>(&sh[r0 * 136 + c0]) =
                    __floats2bfloat162_rn(v00, v01);
                *reinterpret_cast<__nv_bfloat162*>(&sh[(r0 + 8) * 136 + c0]) =
                    __floats2bfloat162_rn(v10, v11);
            }
        }
    }
    __syncthreads();

    // ---- GEMM2: gb = h * W2^T ----
    float acc2[2][8][4];
#pragma unroll
    for (int mt = 0; mt < 2; mt++)
#pragma unroll
        for (int nt = 0; nt < 8; nt++)
#pragma unroll
            for (int i = 0; i < 4; i++) acc2[mt][nt][i] = 0.f;
#pragma unroll
    for (int kt = 0; kt < 8; kt++) {
        unsigned A[2][4];
        ldsm4(A[0], sbase + ((mbase + r16) * 136 + khalf + kt * 16) * 2);
        ldsm4(A[1], sbase + ((mbase + 16 + r16) * 136 + khalf + kt * 16) * 2);
#pragma unroll
        for (int nt = 0; nt < 8; nt++) {
            uint2 bb = __ldg(&g_fB2[(kt * 16 + ncol * 8 + nt) * 32 + lane]);
            mma_bf16(acc2[0][nt], A[0], bb.x, bb.y);
            mma_bf16(acc2[1][nt], A[1], bb.x, bb.y);
        }
    }
    __syncthreads();  // all ldsm reads of sh complete before overwrite

    // epilogue2: + bias -> sh (bf16)
#pragma unroll
    for (int mt = 0; mt < 2; mt++) {
        const int r0 = mbase + mt * 16 + gid;
#pragma unroll
        for (int nt = 0; nt < 8; nt++) {
            int n0 = (ncol * 8 + nt) * 8 + tig * 2;
            float bb0 = (n0 < 64) ? __ldg(&b_gamma[n0]) : __ldg(&b_beta[n0 - 64]);
            float bb1 = (n0 + 1 < 64) ? __ldg(&b_gamma[n0 + 1]) : __ldg(&b_beta[n0 + 1 - 64]);
            *reinterpret_cast<__nv_bfloat162*>(&sh[r0 * 136 + n0]) =
                __floats2bfloat162_rn(acc2[mt][nt][0] + bb0, acc2[mt][nt][1] + bb1);
            *reinterpret_cast<__nv_bfloat162*>(&sh[(r0 + 8) * 136 + n0]) =
                __floats2bfloat162_rn(acc2[mt][nt][2] + bb0, acc2[mt][nt][3] + bb1);
        }
    }
    __syncthreads();

    // store packed (gamma,beta), coalesced per channel plane
    {
        unsigned* gbp = g_gb + (((size_t)b * CN) << 16) + px0;
#pragma unroll 4
        for (int e = tid; e < 8192; e += 256) {
            int c = e >> 7;
            int px = e & 127;
            float gamma = __bfloat162float(sh[px * 136 + c]);
            float beta  = __bfloat162float(sh[px * 136 + 64 + c]);
            gbp[((size_t)c << 16) + px] = pack_bf16x2(gamma, beta);
        }
    }
}

// ---------------- fused instance-norm stats + apply (one block per (b,c) plane) ----------------
__global__ void __launch_bounds__(512, 2)
norm_apply_kernel(const float* __restrict__ x, float* __restrict__ out) {
    const int bc = blockIdx.x;
    const int tid = threadIdx.x;
    const float4* xp = reinterpret_cast<const float4*>(x + (size_t)bc * 65536);
    float4* op = reinterpret_cast<float4*>(out + (size_t)bc * 65536);
    const uint4* gbp = reinterpret_cast<const uint4*>(g_gb + ((size_t)bc << 16));

    float s = 0.f, q = 0.f;
#pragma unroll 8
    for (int i = tid; i < 16384; i += 512) {
        float4 v = xp[i];
        s += (v.x + v.y) + (v.z + v.w);
        q += v.x * v.x + v.y * v.y + v.z * v.z + v.w * v.w;
    }
#pragma unroll
    for (int o = 16; o > 0; o >>= 1) {
        s += __shfl_down_sync(0xffffffffu, s, o);
        q += __shfl_down_sync(0xffffffffu, q, o);
    }
    __shared__ float ws[16], wq[16], stat[2];
    int w = tid >> 5;
    if ((tid & 31) == 0) { ws[w] = s; wq[w] = q; }
    __syncthreads();
    if (tid == 0) {
        float S = 0.f, Q = 0.f;
#pragma unroll
        for (int i = 0; i < 16; i++) { S += ws[i]; Q += wq[i]; }
        float mu = S * (1.f / 65536.f);
        float var = Q * (1.f / 65536.f) - mu * mu;
        stat[0] = mu;
        stat[1] = rsqrtf(var + EPSV);
    }
    __syncthreads();
    const float mu = stat[0];
    const float rstd = stat[1];

#pragma unroll 4
    for (int i = tid; i < 16384; i += 512) {
        float4 v = xp[i];
        uint4 g = gbp[i];
        float4 r;
        {
            __nv_bfloat162 p = *reinterpret_cast<__nv_bfloat162*>(&g.x);
            float xn = (v.x - mu) * rstd;
            r.x = xn * (1.f + __bfloat162float(p.x)) + __bfloat162float(p.y) + 0.1f * v.x;
        }
        {
            __nv_bfloat162 p = *reinterpret_cast<__nv_bfloat162*>(&g.y);
            float xn = (v.y - mu) * rstd;
            r.y = xn * (1.f + __bfloat162float(p.x)) + __bfloat162float(p.y) + 0.1f * v.y;
        }
        {
            __nv_bfloat162 p = *reinterpret_cast<__nv_bfloat162*>(&g.z);
            float xn = (v.z - mu) * rstd;
            r.z = xn * (1.f + __bfloat162float(p.x)) + __bfloat162float(p.y) + 0.1f * v.z;
        }
        {
            __nv_bfloat162 p = *reinterpret_cast<__nv_bfloat162*>(&g.w);
            float xn = (v.w - mu) * rstd;
            r.w = xn * (1.f + __bfloat162float(p.x)) + __bfloat162float(p.y) + 0.1f * v.w;
        }
        op[i] = r;
    }
}

extern "C" void kernel_launch(void* const* d_in, const int* in_sizes, int n_in,
                              void* d_out, int out_size) {
    (void)in_sizes; (void)n_in; (void)out_size;
    const float* x        = (const float*)d_in[0];
    const float* hm       = (const float*)d_in[1];
    const float* F        = (const float*)d_in[2];
    const float* w_shared = (const float*)d_in[3];
    const float* b_shared = (const float*)d_in[4];
    const float* w_gamma  = (const float*)d_in[5];
    const float* b_gamma  = (const float*)d_in[6];
    const float* w_beta   = (const float*)d_in[7];
    const float* b_beta   = (const float*)d_in[8];
    float* out = (float*)d_out;

    prep_kernel<<<1, 256>>>(F, w_shared, w_gamma, w_beta);
    dim3 fgrid(16, 16, 64);
    fir_kernel<<<fgrid, 256>>>(hm);
    dim3 ggrid(512, 8);
    gemm_kernel<<<ggrid, 256>>>(b_shared, b_gamma, b_beta);
    norm_apply_kernel<<<Bn * CN, 512>>>(x, out);
}

// round 8
// speedup vs baseline: 1.9083x; 1.2123x over previous
#include <cuda_runtime.h>
#include <cuda_bf16.h>
#include <cstdint>

#define Bn 8
#define CN 64
#define CL 32
#define CH 128
#define Himg 256
#define HMimg 512
#define SLOPE 0.2f
#define GAINF 1.4142135623730951f
#define EPSV 1e-5f

__device__ float g_a[12];
__device__ uint2 g_fB1[1024];   // [kt2][nt16][lane32] -> (pair0,pair1) bf16x2
__device__ uint2 g_fB2[4096];   // [kt8][nt16][lane32] -> (pair0,pair1) bf16x2
// layout: [b][chgroup(8)][px(65536)][4ch] bf16  (one uint2 per (px,group))
__device__ __nv_bfloat16 g_v[(size_t)Bn * 8 * 65536 * 4];
__device__ unsigned g_gb[(size_t)Bn * CN * 65536];      // packed (gamma,beta) bf16x2

static __device__ __forceinline__ unsigned pack_bf16x2(float a, float b) {
    __nv_bfloat162 t = __floats2bfloat162_rn(a, b);
    return *reinterpret_cast<unsigned*>(&t);
}

// ---------------- prep: filter factorization + weight fragments ----------------
__global__ void prep_kernel(const float* __restrict__ F,
                            const float* __restrict__ w_shared,
                            const float* __restrict__ w_gamma,
                            const float* __restrict__ w_beta) {
    int tid = threadIdx.x;
    // F = outer(g,g); flipped 1D filter a[i] = g[11-i] = F[11-i][5]/sqrt(F[5][5])
    if (tid < 12) {
        g_a[tid] = F[(11 - tid) * 12 + 5] * rsqrtf(F[5 * 12 + 5]);
    }
    unsigned* B1 = reinterpret_cast<unsigned*>(g_fB1);
    for (int idx = tid; idx < 2048; idx += blockDim.x) {
        int pair = idx & 1;
        int lane = (idx >> 1) & 31;
        int nt = (idx >> 6) & 15;
        int kt = idx >> 10;
        int gid = lane >> 2, tig = lane & 3;
        int n = nt * 8 + gid;
        int k = kt * 16 + tig * 2 + pair * 8;
        B1[idx] = pack_bf16x2(w_shared[n * CL + k], w_shared[n * CL + k + 1]);
    }
    unsigned* B2 = reinterpret_cast<unsigned*>(g_fB2);
    for (int idx = tid; idx < 8192; idx += blockDim.x) {
        int pair = idx & 1;
        int lane = (idx >> 1) & 31;
        int nt = (idx >> 6) & 15;
        int kt = idx >> 10;
        int gid = lane >> 2, tig = lane & 3;
        int n = nt * 8 + gid;
        int k = kt * 16 + tig * 2 + pair * 8;
        float v0, v1;
        if (n < 64) { v0 = w_gamma[n * CH + k]; v1 = w_gamma[n * CH + k + 1]; }
        else        { v0 = w_beta[(n - 64) * CH + k]; v1 = w_beta[(n - 64) * CH + k + 1]; }
        B2[idx] = pack_bf16x2(v0, v1);
    }
}

// ---------------- FIR downsample: 16x32 out-tile, 4 channels per block ----------------
// grid (8, 16, 64): x=col-tile(32 wide), y=row-tile(16), z = b*8 + chgroup
// Horizontal FIR reads hm DIRECTLY from gmem (aligned float4, L1 absorbs overlap).
__global__ void __launch_bounds__(256, 4)
fir_kernel(const float* __restrict__ hm) {
    __shared__ float sint[4 * 42 * 32];   // 21504 B
    __shared__ float sres[4 * 16 * 32];   //  8192 B

    const int tid = threadIdx.x;
    const int x0 = blockIdx.x * 32;
    const int y0 = blockIdx.y * 16;
    const int b = blockIdx.z >> 3;
    const int g = blockIdx.z & 7;

    float areg[12];
#pragma unroll
    for (int j = 0; j < 12; j++) areg[j] = __ldg(&g_a[j]);

    const float* hmb = hm + ((size_t)(b * CL + g * 4)) * (HMimg * HMimg);
    const bool interior = (blockIdx.x >= 1) & (blockIdx.x <= 6) &
                          (blockIdx.y >= 1) & (blockIdx.y <= 14);

    // phase 1: horizontal FIR (stride 2) straight from gmem
    // tasks: 4ch x 42rows x 8 quads = 1344; quad = 4 out-cols from 24 input floats
    for (int t = tid; t < 1344; t += 256) {
        int c = t / 336;
        int rem = t - c * 336;
        int r = rem >> 3;
        int oq = rem & 7;
        int gr = 2 * y0 - 5 + r;
        int cb = 2 * x0 - 8 + oq * 8;   // 16B-aligned base column
        float w[24];
        if (interior) {
            const float4* p = reinterpret_cast<const float4*>(
                hmb + (size_t)c * (HMimg * HMimg) + (size_t)gr * HMimg + cb);
#pragma unroll
            for (int q5 = 0; q5 < 6; q5++) {
                float4 v = __ldg(&p[q5]);
                w[q5 * 4 + 0] = v.x; w[q5 * 4 + 1] = v.y;
                w[q5 * 4 + 2] = v.z; w[q5 * 4 + 3] = v.w;
            }
        } else {
            const float* rp = hmb + (size_t)c * (HMimg * HMimg) + (size_t)gr * HMimg;
            bool rok = ((unsigned)gr < 512u);
#pragma unroll
            for (int i = 0; i < 24; i++) {
                int col = cb + i;
                w[i] = (rok && (unsigned)col < 512u) ? __ldg(rp + col) : 0.f;
            }
        }
        float o[4];
#pragma unroll
        for (int q = 0; q < 4; q++) {
            float a0 = 0.f, a1 = 0.f;
#pragma unroll
            for (int j = 0; j < 6; j++) {
                a0 += w[2 * q + 3 + j] * areg[j];
                a1 += w[2 * q + 9 + j] * areg[j + 6];
            }
            o[q] = a0 + a1;
        }
        *reinterpret_cast<float4*>(&sint[(c * 42 + r) * 32 + oq * 4]) =
            make_float4(o[0], o[1], o[2], o[3]);
    }
    __syncthreads();

    // phase 2: vertical FIR (stride 2), 4 output-rows per task (one column)
    for (int v = tid; v < 512; v += 256) {
        int c = v >> 7;
        int rem = v & 127;
        int og = rem >> 5;         // out rows og*4 .. og*4+3
        int ox = rem & 31;
        const float* ip = &sint[(c * 42 + og * 8) * 32 + ox];
        float w[18];
#pragma unroll
        for (int j = 0; j < 18; j++) w[j] = ip[j * 32];
#pragma unroll
        for (int q = 0; q < 4; q++) {
            float a0 = 0.f, a1 = 0.f;
#pragma unroll
            for (int j = 0; j < 6; j++) {
                a0 += w[2 * q + j] * areg[j];
                a1 += w[2 * q + 6 + j] * areg[j + 6];
            }
            sres[(c * 16 + og * 4 + q) * 32 + ox] = a0 + a1;
        }
    }
    __syncthreads();

    // phase 3: pack 4 channels per pixel, coalesced store
    for (int p = tid; p < 512; p += 256) {
        int orow = p >> 5;
        int ox = p & 31;
        uint2 val;
        val.x = pack_bf16x2(sres[(0 * 16 + orow) * 32 + ox], sres[(1 * 16 + orow) * 32 + ox]);
        val.y = pack_bf16x2(sres[(2 * 16 + orow) * 32 + ox], sres[(3 * 16 + orow) * 32 + ox]);
        size_t px = (size_t)(y0 + orow) * Himg + (x0 + ox);
        reinterpret_cast<uint2*>(g_v)[((size_t)blockIdx.z << 16) + px] = val;
    }
}

// ---------------- mma helpers ----------------
static __device__ __forceinline__ void ldsm4(unsigned r[4], unsigned addr) {
    asm volatile("ldmatrix.sync.aligned.m8n8.x4.shared.b16 {%0,%1,%2,%3}, [%4];"
                 : "=r"(r[0]), "=r"(r[1]), "=r"(r[2]), "=r"(r[3])
                 : "r"(addr) : "memory");
}
static __device__ __forceinline__ void mma_bf16(float c[4], const unsigned a[4],
                                                unsigned b0, unsigned b1) {
    asm("mma.sync.aligned.m16n8k16.row.col.f32.bf16.bf16.f32 "
        "{%0,%1,%2,%3}, {%4,%5,%6,%7}, {%8,%9}, {%0,%1,%2,%3};"
        : "+f"(c[0]), "+f"(c[1]), "+f"(c[2]), "+f"(c[3])
        : "r"(a[0]), "r"(a[1]), "r"(a[2]), "r"(a[3]), "r"(b0), "r"(b1));
}

// ---------------- GEMM1 + GEMM2 -> packed gamma/beta ----------------
// grid (512, 8): 128 consecutive px per block. 8 warps as 4(M) x 2(N).
__global__ void __launch_bounds__(256, 2)
gemm_kernel(const float* __restrict__ b_shared,
            const float* __restrict__ b_gamma,
            const float* __restrict__ b_beta) {
    __shared__ __nv_bfloat16 sh[128 * 136];      // also aliased as sv[128][40] during A-stage
    __nv_bfloat16* sv = sh;

    const int tid = threadIdx.x;
    const int lane = tid & 31;
    const int warp = tid >> 5;
    const int b = blockIdx.y;
    const int px0 = blockIdx.x * 128;

    // stage A: v from [b][g][px][4] layout -> sv[128][40]
    {
        const uint2* src = reinterpret_cast<const uint2*>(g_v) + (((size_t)b * 8) << 16) + px0;
        for (int e = tid; e < 1024; e += 256) {
            int g = e >> 7, px = e & 127;
            uint2 v = __ldg(&src[((size_t)g << 16) + px]);
            *reinterpret_cast<uint2*>(&sv[px * 40 + g * 4]) = v;
        }
    }
    __syncthreads();

    const int mrow = warp & 3;            // 0..3 -> M offset 32*mrow
    const int ncol = warp >> 2;           // 0..1 -> N offset 64*ncol
    const int mbase = mrow * 32;
    const int gid = lane >> 2, tig = lane & 3;
    const int r16 = lane & 15;
    const int khalf = (lane >> 4) << 3;

    unsigned sbase = (unsigned)__cvta_generic_to_shared(sh);

    // ---- GEMM1: load A fragments up-front (sv will be overwritten by sh) ----
    unsigned A1[2][2][4];
#pragma unroll
    for (int mt = 0; mt < 2; mt++)
#pragma unroll
        for (int kt = 0; kt < 2; kt++)
            ldsm4(A1[mt][kt], sbase + ((mbase + mt * 16 + r16) * 40 + khalf + kt * 16) * 2);
    __syncthreads();

    {
        float acc[2][8][4];
#pragma unroll
        for (int mt = 0; mt < 2; mt++)
#pragma unroll
            for (int nt = 0; nt < 8; nt++)
#pragma unroll
                for (int i = 0; i < 4; i++) acc[mt][nt][i] = 0.f;
#pragma unroll
        for (int kt = 0; kt < 2; kt++)
#pragma unroll
            for (int nt = 0; nt < 8; nt++) {
                uint2 bb = __ldg(&g_fB1[(kt * 16 + ncol * 8 + nt) * 32 + lane]);
                mma_bf16(acc[0][nt], A1[0][kt], bb.x, bb.y);
                mma_bf16(acc[1][nt], A1[1][kt], bb.x, bb.y);
            }
        // epilogue1: bias + lrelu*gain -> sh (bf16)
#pragma unroll
        for (int mt = 0; mt < 2; mt++) {
            const int r0 = mbase + mt * 16 + gid;
#pragma unroll
            for (int nt = 0; nt < 8; nt++) {
                int c0 = (ncol * 8 + nt) * 8 + tig * 2;
                float bb0 = __ldg(&b_shared[c0]), bb1 = __ldg(&b_shared[c0 + 1]);
                float v00 = acc[mt][nt][0] + bb0, v01 = acc[mt][nt][1] + bb1;
                float v10 = acc[mt][nt][2] + bb0, v11 = acc[mt][nt][3] + bb1;
                v00 = (v00 >= 0.f ? v00 : v00 * SLOPE) * GAINF;
                v01 = (v01 >= 0.f ? v01 : v01 * SLOPE) * GAINF;
                v10 = (v10 >= 0.f ? v10 : v10 * SLOPE) * GAINF;
                v11 = (v11 >= 0.f ? v11 : v11 * SLOPE) * GAINF;
                *reinterpret_cast<__nv_bfloat162*>(&sh[r0 * 136 + c0]) =
                    __floats2bfloat162_rn(v00, v01);
                *reinterpret_cast<__nv_bfloat162*>(&sh[(r0 + 8) * 136 + c0]) =
                    __floats2bfloat162_rn(v10, v11);
            }
        }
    }
    __syncthreads();

    // ---- GEMM2: gb = h * W2^T ----
    float acc2[2][8][4];
#pragma unroll
    for (int mt = 0; mt < 2; mt++)
#pragma unroll
        for (int nt = 0; nt < 8; nt++)
#pragma unroll
            for (int i = 0; i < 4; i++) acc2[mt][nt][i] = 0.f;
#pragma unroll
    for (int kt = 0; kt < 8; kt++) {
        unsigned A[2][4];
        ldsm4(A[0], sbase + ((mbase + r16) * 136 + khalf + kt * 16) * 2);
        ldsm4(A[1], sbase + ((mbase + 16 + r16) * 136 + khalf + kt * 16) * 2);
#pragma unroll
        for (int nt = 0; nt < 8; nt++) {
            uint2 bb = __ldg(&g_fB2[(kt * 16 + ncol * 8 + nt) * 32 + lane]);
            mma_bf16(acc2[0][nt], A[0], bb.x, bb.y);
            mma_bf16(acc2[1][nt], A[1], bb.x, bb.y);
        }
    }
    __syncthreads();  // all ldsm reads of sh complete before overwrite

    // epilogue2: + bias -> sh (bf16)
#pragma unroll
    for (int mt = 0; mt < 2; mt++) {
        const int r0 = mbase + mt * 16 + gid;
#pragma unroll
        for (int nt = 0; nt < 8; nt++) {
            int n0 = (ncol * 8 + nt) * 8 + tig * 2;
            float bb0 = (n0 < 64) ? __ldg(&b_gamma[n0]) : __ldg(&b_beta[n0 - 64]);
            float bb1 = (n0 + 1 < 64) ? __ldg(&b_gamma[n0 + 1]) : __ldg(&b_beta[n0 + 1 - 64]);
            *reinterpret_cast<__nv_bfloat162*>(&sh[r0 * 136 + n0]) =
                __floats2bfloat162_rn(acc2[mt][nt][0] + bb0, acc2[mt][nt][1] + bb1);
            *reinterpret_cast<__nv_bfloat162*>(&sh[(r0 + 8) * 136 + n0]) =
                __floats2bfloat162_rn(acc2[mt][nt][2] + bb0, acc2[mt][nt][3] + bb1);
        }
    }
    __syncthreads();

    // store packed (gamma,beta), coalesced per channel plane
    {
        unsigned* gbp = g_gb + (((size_t)b * CN) << 16) + px0;
#pragma unroll 4
        for (int e = tid; e < 8192; e += 256) {
            int c = e >> 7;
            int px = e & 127;
            float gamma = __bfloat162float(sh[px * 136 + c]);
            float beta  = __bfloat162float(sh[px * 136 + 64 + c]);
            gbp[((size_t)c << 16) + px] = pack_bf16x2(gamma, beta);
        }
    }
}

// ---------------- fused instance-norm stats + apply (one block per (b,c) plane) ----------------
__global__ void __launch_bounds__(512, 2)
norm_apply_kernel(const float* __restrict__ x, float* __restrict__ out) {
    const int bc = blockIdx.x;
    const int tid = threadIdx.x;
    const float4* xp = reinterpret_cast<const float4*>(x + (size_t)bc * 65536);
    float4* op = reinterpret_cast<float4*>(out + (size_t)bc * 65536);
    const uint4* gbp = reinterpret_cast<const uint4*>(g_gb + ((size_t)bc << 16));

    float s = 0.f, q = 0.f;
#pragma unroll 8
    for (int i = tid; i < 16384; i += 512) {
        float4 v = xp[i];
        s += (v.x + v.y) + (v.z + v.w);
        q += v.x * v.x + v.y * v.y + v.z * v.z + v.w * v.w;
    }
#pragma unroll
    for (int o = 16; o > 0; o >>= 1) {
        s += __shfl_down_sync(0xffffffffu, s, o);
        q += __shfl_down_sync(0xffffffffu, q, o);
    }
    __shared__ float ws[16], wq[16], stat[2];
    int w = tid >> 5;
    if ((tid & 31) == 0) { ws[w] = s; wq[w] = q; }
    __syncthreads();
    if (tid == 0) {
        float S = 0.f, Q = 0.f;
#pragma unroll
        for (int i = 0; i < 16; i++) { S += ws[i]; Q += wq[i]; }
        float mu = S * (1.f / 65536.f);
        float var = Q * (1.f / 65536.f) - mu * mu;
        stat[0] = mu;
        stat[1] = rsqrtf(var + EPSV);
    }
    __syncthreads();
    const float mu = stat[0];
    const float rstd = stat[1];

#pragma unroll 4
    for (int i = tid; i < 16384; i += 512) {
        float4 v = xp[i];
        uint4 g = gbp[i];
        float4 r;
        {
            __nv_bfloat162 p = *reinterpret_cast<__nv_bfloat162*>(&g.x);
            float xn = (v.x - mu) * rstd;
            r.x = xn * (1.f + __bfloat162float(p.x)) + __bfloat162float(p.y) + 0.1f * v.x;
        }
        {
            __nv_bfloat162 p = *reinterpret_cast<__nv_bfloat162*>(&g.y);
            float xn = (v.y - mu) * rstd;
            r.y = xn * (1.f + __bfloat162float(p.x)) + __bfloat162float(p.y) + 0.1f * v.y;
        }
        {
            __nv_bfloat162 p = *reinterpret_cast<__nv_bfloat162*>(&g.z);
            float xn = (v.z - mu) * rstd;
            r.z = xn * (1.f + __bfloat162float(p.x)) + __bfloat162float(p.y) + 0.1f * v.z;
        }
        {
            __nv_bfloat162 p = *reinterpret_cast<__nv_bfloat162*>(&g.w);
            float xn = (v.w - mu) * rstd;
            r.w = xn * (1.f + __bfloat162float(p.x)) + __bfloat162float(p.y) + 0.1f * v.w;
        }
        op[i] = r;
    }
}

extern "C" void kernel_launch(void* const* d_in, const int* in_sizes, int n_in,
                              void* d_out, int out_size) {
    (void)in_sizes; (void)n_in; (void)out_size;
    const float* x        = (const float*)d_in[0];
    const float* hm       = (const float*)d_in[1];
    const float* F        = (const float*)d_in[2];
    const float* w_shared = (const float*)d_in[3];
    const float* b_shared = (const float*)d_in[4];
    const float* w_gamma  = (const float*)d_in[5];
    const float* b_gamma  = (const float*)d_in[6];
    const float* w_beta   = (const float*)d_in[7];
    const float* b_beta   = (const float*)d_in[8];
    float* out = (float*)d_out;

    prep_kernel<<<1, 256>>>(F, w_shared, w_gamma, w_beta);
    dim3 fgrid(8, 16, 64);
    fir_kernel<<<fgrid, 256>>>(hm);
    dim3 ggrid(512, 8);
    gemm_kernel<<<ggrid, 256>>>(b_shared, b_gamma, b_beta);
    norm_apply_kernel<<<Bn * CN, 512>>>(x, out);
}